// round 2
// baseline (speedup 1.0000x reference)
#include <cuda_runtime.h>

#define BATCH 36
#define TWIN 60
#define DECAY 0.3f
#define THRESH 0.5f

// ---------------- persistent LIAF state: "pre" = decayed, spike-gated membrane ----
// pre = (m > THRESH) ? 0 : m*DECAY  ; next-step membrane m' = pre + u  (bit-exact
// vs reference m*DECAY*(1-s)+u since s is exactly 0.0/1.0)
__device__ __align__(16) float g_c0_pre[BATCH*64*32*32];
__device__ __align__(16) float g_c1_pre[BATCH*128*32*32];
__device__ __align__(16) float g_p1_pre[BATCH*128*16*16];
__device__ __align__(16) float g_c2_pre[BATCH*128*16*16];
__device__ __align__(16) float g_p2_pre[BATCH*128*8*8];
__device__ __align__(16) float g_h1_pre[BATCH*256];
__device__ __align__(16) float g_h2_pre[BATCH*11];
__device__ __align__(16) float g_acc[BATCH*11];

// ---------------- inter-layer activations (overwritten each step) ----------------
__device__ __align__(16) float g_act0 [BATCH*64*32*32];   // conv0 out (conv1 input)
__device__ __align__(16) float g_actp1[BATCH*128*16*16];  // pool1 out (conv2 input)
__device__ __align__(16) float g_actp2[BATCH*128*8*8];    // pool2 out (fc1 input)
__device__ __align__(16) float g_acth1[BATCH*256];        // fc1 out  (fc2 input)

__device__ __forceinline__ float liaf_pre(float u, float* prep) {
    float m = *prep + u;
    *prep = (m > THRESH) ? 0.0f : m * DECAY;
    return fmaxf(m, 0.0f);
}

// ---------------- zero state ----------------
__global__ void zero_state_kernel() {
    int i = blockIdx.x * blockDim.x + threadIdx.x;
    if (i < BATCH*64*32*32)  g_c0_pre[i] = 0.f;
    if (i < BATCH*128*32*32) g_c1_pre[i] = 0.f;
    if (i < BATCH*128*16*16) { g_p1_pre[i] = 0.f; g_c2_pre[i] = 0.f; }
    if (i < BATCH*128*8*8)   g_p2_pre[i] = 0.f;
    if (i < BATCH*256)       g_h1_pre[i] = 0.f;
    if (i < BATCH*11)        { g_h2_pre[i] = 0.f; g_acc[i] = 0.f; }
}

// ---------------- conv0: binarize + 2->64 conv + LIAF ----------------
// grid (16, 36), block 256: thread = pixel(64) x ocgroup(4 of 16ch)
__global__ __launch_bounds__(256) void conv0_kernel(
    const float* __restrict__ data, const float* __restrict__ W0,
    const float* __restrict__ b0, int t)
{
    __shared__ float xs[2][10][12];
    __shared__ float ws[64][19];
    int tile = blockIdx.x, b = blockIdx.y;
    int ty0 = (tile >> 2) * 8, tx0 = (tile & 3) * 8;
    int tid = threadIdx.x;

    for (int i = tid; i < 200; i += 256) {
        int ic = i / 100, r = (i / 10) % 10, c = i % 10;
        int gy = ty0 + r - 1, gx = tx0 + c - 1;
        float v = 0.f;
        if ((unsigned)gy < 32u && (unsigned)gx < 32u) {
            float d = data[(size_t)((((b*2 + ic)*32 + gy)*32 + gx)) * TWIN + t];
            v = (d > 1.0f) ? 1.0f : 0.0f;
        }
        xs[ic][r][c] = v;
    }
    for (int i = tid; i < 1152; i += 256) {
        int oc = i / 18, r = i % 18;
        ws[oc][r] = W0[i];
    }
    __syncthreads();

    int p  = tid & 63;
    int cg = tid >> 6;
    int py = p >> 3, px = p & 7;
    int oc0 = cg * 16;

    float acc[16];
#pragma unroll
    for (int o = 0; o < 16; o++) acc[o] = 0.f;

#pragma unroll
    for (int ic = 0; ic < 2; ic++) {
        float xr[9];
#pragma unroll
        for (int r = 0; r < 3; r++)
#pragma unroll
            for (int c = 0; c < 3; c++)
                xr[r*3 + c] = xs[ic][py + r][px + c];
#pragma unroll
        for (int k = 0; k < 9; k++) {
            float x = xr[k];
#pragma unroll
            for (int o = 0; o < 16; o++)
                acc[o] = fmaf(x, ws[oc0 + o][ic*9 + k], acc[o]);
        }
    }

    int gy = ty0 + py, gx = tx0 + px;
#pragma unroll
    for (int o = 0; o < 16; o++) {
        int oc = oc0 + o;
        int idx = ((b*64 + oc)*32 + gy)*32 + gx;
        float u = acc[o] + b0[oc];
        g_act0[idx] = liaf_pre(u, &g_c0_pre[idx]);
    }
}

// ---------------- generic 3x3 conv (CIN->64 oc half) + LIAF + 2x2 pool + LIAF ----
// block 128: thread = 2x2 pixel quad (16 quads) x 8 oc (8 groups); tile 8x8.
// blockIdx.x = tileIdx*2 + ocHalf ; ocbase = ocHalf*64.
// Skewed smem row layout for weights: rowoff(oc) = oc*76 + (oc>>3)*4
// (float4-alignable, and the two broadcast addresses per warp land in
//  different banks).
template<int CIN, int HW>
__device__ __forceinline__ void conv_pool_body(
    const float* __restrict__ in, const float* __restrict__ W,
    const float* __restrict__ bias,
    float* __restrict__ conv_pre,   // conv LIAF state, [B,128,HW,HW]
    float* __restrict__ pool_pre,   // pool LIAF state, [B,128,HW/2,HW/2]
    float* __restrict__ pool_out)   // pooled output,   [B,128,HW/2,HW/2]
{
    __shared__ float xs[8][10][12];
    __shared__ float ws[64*76 + 8*4];

    const int TPD = HW / 8;
    int bx = blockIdx.x, b = blockIdx.y;
    int ochalf = bx & 1;
    int tile = bx >> 1;
    int ty0 = (tile / TPD) * 8, tx0 = (tile % TPD) * 8;
    int ocbase = ochalf * 64;
    int tid = threadIdx.x;

    int qp = tid & 15, cg = tid >> 4;      // cg 0..7
    int qy = (qp >> 2) * 2, qx = (qp & 3) * 2;
    int oc0 = cg * 8;                      // local oc

    float acc[2][2][8];
#pragma unroll
    for (int py = 0; py < 2; py++)
#pragma unroll
        for (int px = 0; px < 2; px++)
#pragma unroll
            for (int o = 0; o < 8; o++) acc[py][px][o] = 0.f;

    const float4* W4 = (const float4*)W;

    for (int ch = 0; ch < CIN/8; ch++) {
        __syncthreads();
        // input tile 8 ch x 10x10 (halo, zero-pad)
        for (int i = tid; i < 800; i += 128) {
            int icl = i / 100, r = (i / 10) % 10, c = i % 10;
            int gy = ty0 + r - 1, gx = tx0 + c - 1;
            float v = 0.f;
            if ((unsigned)gy < (unsigned)HW && (unsigned)gx < (unsigned)HW)
                v = in[((b*CIN + ch*8 + icl)*HW + gy)*HW + gx];
            xs[icl][r][c] = v;
        }
        // weights: 64 oc x (8 ic x 9) = 1152 float4, coalesced
        for (int i = tid; i < 1152; i += 128) {
            int oc = i / 18, j = i % 18;
            int base4 = (((ocbase + oc)*CIN + ch*8)*9) >> 2;
            float4 v = W4[base4 + j];
            *(float4*)&ws[oc*76 + (oc>>3)*4 + j*4] = v;
        }
        __syncthreads();

#pragma unroll
        for (int icl = 0; icl < 8; icl++) {
            float xr[4][4];
#pragma unroll
            for (int r = 0; r < 4; r++)
#pragma unroll
                for (int c = 0; c < 4; c++)
                    xr[r][c] = xs[icl][qy + r][qx + c];
#pragma unroll
            for (int ky = 0; ky < 3; ky++)
#pragma unroll
                for (int kx = 0; kx < 3; kx++) {
                    float w8[8];
#pragma unroll
                    for (int o = 0; o < 8; o++) {
                        int oc = oc0 + o;
                        w8[o] = ws[oc*76 + (oc>>3)*4 + icl*9 + ky*3 + kx];
                    }
#pragma unroll
                    for (int py = 0; py < 2; py++)
#pragma unroll
                        for (int px = 0; px < 2; px++) {
                            float x = xr[py + ky][px + kx];
#pragma unroll
                            for (int o = 0; o < 8; o++)
                                acc[py][px][o] = fmaf(x, w8[o], acc[py][px][o]);
                        }
                }
        }
    }

    // epilogue: conv LIAF per pixel, then 2x2 avg pool + pool LIAF (fused)
    int py2 = (ty0 + qy) >> 1, px2 = (tx0 + qx) >> 1;
#pragma unroll
    for (int o = 0; o < 8; o++) {
        int oc = ocbase + oc0 + o;
        float bv = bias[oc];
        float a[2][2];
#pragma unroll
        for (int py = 0; py < 2; py++)
#pragma unroll
            for (int px = 0; px < 2; px++) {
                int gy = ty0 + qy + py, gx = tx0 + qx + px;
                int idx = ((b*128 + oc)*HW + gy)*HW + gx;
                a[py][px] = liaf_pre(acc[py][px][o] + bv, &conv_pre[idx]);
            }
        // identical order to reference pool: ((v00+v01)+v10)+v11
        float u = 0.25f * (((a[0][0] + a[0][1]) + a[1][0]) + a[1][1]);
        int pidx = ((b*128 + oc)*(HW/2) + py2)*(HW/2) + px2;
        pool_out[pidx] = liaf_pre(u, &pool_pre[pidx]);
    }
}

__global__ __launch_bounds__(128, 4) void conv1_kernel(
    const float* __restrict__ W, const float* __restrict__ bias)
{
    conv_pool_body<64, 32>(g_act0, W, bias, g_c1_pre, g_p1_pre, g_actp1);
}

__global__ __launch_bounds__(128, 4) void conv2_kernel(
    const float* __restrict__ W, const float* __restrict__ bias)
{
    conv_pool_body<128, 16>(g_actp1, W, bias, g_c2_pre, g_p2_pre, g_actp2);
}

// ---------------- FC1: 8192 -> 256 + LIAF ----------------
// grid 64, block 128 (4 warps = 4 outputs/block), loop over batches.
// Per-(b,o) accumulation order identical to previous passing version.
__global__ __launch_bounds__(128) void fc1_kernel(
    const float* __restrict__ Wf1, const float* __restrict__ bf1)
{
    int warp = threadIdx.x >> 5, lane = threadIdx.x & 31;
    int o = blockIdx.x * 4 + warp;
    const float4* wp = (const float4*)(Wf1 + (size_t)o * 8192);
    float bv = bf1[o];
    for (int b = 0; b < BATCH; b++) {
        const float4* xp = (const float4*)(g_actp2 + (size_t)b * 8192);
        float s = 0.f;
#pragma unroll 8
        for (int i = lane; i < 2048; i += 32) {
            float4 x = xp[i], w = wp[i];
            s += x.x*w.x; s += x.y*w.y; s += x.z*w.z; s += x.w*w.w;
        }
#pragma unroll
        for (int off = 16; off; off >>= 1) s += __shfl_down_sync(0xffffffffu, s, off);
        if (lane == 0) {
            int idx = b*256 + o;
            g_acth1[idx] = liaf_pre(s + bv, &g_h1_pre[idx]);
        }
    }
}

// ---------------- FC2: 256 -> 11 + LIAF + accumulate ----------------
__global__ void fc2_kernel(const float* __restrict__ Wf2, const float* __restrict__ bf2) {
    int b = blockIdx.x;
    int warp = threadIdx.x >> 5, lane = threadIdx.x & 31;
    if (warp >= 11) return;
    float s = 0.f;
#pragma unroll
    for (int k = lane; k < 256; k += 32)
        s += g_acth1[b*256 + k] * Wf2[warp*256 + k];
#pragma unroll
    for (int off = 16; off; off >>= 1) s += __shfl_down_sync(0xffffffffu, s, off);
    if (lane == 0) {
        int idx = b*11 + warp;
        float o = liaf_pre(s + bf2[warp], &g_h2_pre[idx]);
        g_acc[idx] += o;
    }
}

// ---------------- finalize ----------------
__global__ void finalize_kernel(float* __restrict__ out) {
    int i = threadIdx.x;
    if (i < BATCH*11) out[i] = g_acc[i] * (1.0f / (float)TWIN);
}

extern "C" void kernel_launch(void* const* d_in, const int* in_sizes, int n_in,
                              void* d_out, int out_size) {
    (void)in_sizes; (void)n_in; (void)out_size;
    const float* data = (const float*)d_in[0];
    // d_in[1] = win (== 60, fixed)
    const float* W0  = (const float*)d_in[2];
    const float* b0  = (const float*)d_in[3];
    const float* W1  = (const float*)d_in[4];
    const float* b1  = (const float*)d_in[5];
    const float* W2  = (const float*)d_in[6];
    const float* b2  = (const float*)d_in[7];
    const float* Wf1 = (const float*)d_in[8];
    const float* bf1 = (const float*)d_in[9];
    const float* Wf2 = (const float*)d_in[10];
    const float* bf2 = (const float*)d_in[11];

    zero_state_kernel<<<(BATCH*128*32*32 + 255)/256, 256>>>();

    for (int t = 0; t < TWIN; t++) {
        conv0_kernel<<<dim3(16, BATCH), 256>>>(data, W0, b0, t);
        conv1_kernel<<<dim3(32, BATCH), 128>>>(W1, b1);   // 16 tiles x 2 oc-halves
        conv2_kernel<<<dim3(8, BATCH), 128>>>(W2, b2);    // 4 tiles x 2 oc-halves
        fc1_kernel<<<64, 128>>>(Wf1, bf1);
        fc2_kernel<<<BATCH, 384>>>(Wf2, bf2);
    }

    finalize_kernel<<<1, 512>>>((float*)d_out);
}

// round 3
// speedup vs baseline: 2.4218x; 2.4218x over previous
#include <cuda_runtime.h>

typedef unsigned long long ull;

#define BATCH 36
#define TWIN 60
#define DECAY 0.3f
#define THRESH 0.5f

// packed f32x2 fma: d = a*b + d per 32-bit lane (bit-exact IEEE fma per lane)
#define FMA2(d, a, b) asm("fma.rn.f32x2 %0, %1, %2, %0;" : "+l"(d) : "l"(a), "l"(b))

union F2 { ull u; float2 f; };

// ---------------- persistent LIAF state: pre = (m>THRESH) ? 0 : m*DECAY ----------
// next membrane m' = pre + u  (bit-exact vs m*DECAY*(1-s)+u, s in {0,1})
__device__ __align__(16) float g_c0_pre[BATCH*64*32*32];
__device__ __align__(16) float g_c1_pre[BATCH*128*32*32];
__device__ __align__(16) float g_p1_pre[BATCH*128*16*16];
__device__ __align__(16) float g_c2_pre[BATCH*128*16*16];
__device__ __align__(16) float g_p2_pre[BATCH*128*8*8];
__device__ __align__(16) float g_h1_pre[BATCH*256];
__device__ __align__(16) float g_h2_pre[BATCH*11];
__device__ __align__(16) float g_acc[BATCH*11];

// ---------------- activations ----------------
__device__ __align__(16) float g_act0 [BATCH*64*32*32];
__device__ __align__(16) float g_actp1[BATCH*128*16*16];
__device__ __align__(16) float g_actp2[BATCH*128*8*8];
__device__ __align__(16) float g_acth1[BATCH*256];

// ---------------- transposed weights: Wt[c][oc], c = ic*9 + k ----------------
__device__ __align__(16) float g_Wt1[576*128];   // conv1: 64*9 x 128
__device__ __align__(16) float g_Wt2[1152*128];  // conv2: 128*9 x 128

__device__ __forceinline__ float liaf_pre(float u, float* prep) {
    float m = *prep + u;
    *prep = (m > THRESH) ? 0.0f : m * DECAY;
    return fmaxf(m, 0.0f);
}

// ---------------- zero state ----------------
__global__ void zero_state_kernel() {
    int i = blockIdx.x * blockDim.x + threadIdx.x;
    if (i < BATCH*64*32*32)  g_c0_pre[i] = 0.f;
    if (i < BATCH*128*32*32) g_c1_pre[i] = 0.f;
    if (i < BATCH*128*16*16) { g_p1_pre[i] = 0.f; g_c2_pre[i] = 0.f; }
    if (i < BATCH*128*8*8)   g_p2_pre[i] = 0.f;
    if (i < BATCH*256)       g_h1_pre[i] = 0.f;
    if (i < BATCH*11)        { g_h2_pre[i] = 0.f; g_acc[i] = 0.f; }
}

// ---------------- weight transpose (once per launch) ----------------
__global__ void prep_weights_kernel(const float* __restrict__ W1,
                                    const float* __restrict__ W2) {
    int i = blockIdx.x * blockDim.x + threadIdx.x;
    if (i < 576*128)  g_Wt1[i] = W1[(i & 127)*576  + (i >> 7)];
    if (i < 1152*128) g_Wt2[i] = W2[(i & 127)*1152 + (i >> 7)];
}

// ---------------- conv0: binarize + 2->64 conv + LIAF ----------------
__global__ __launch_bounds__(256) void conv0_kernel(
    const float* __restrict__ data, const float* __restrict__ W0,
    const float* __restrict__ b0, int t)
{
    __shared__ float xs[2][10][12];
    __shared__ float ws[64][19];
    int tile = blockIdx.x, b = blockIdx.y;
    int ty0 = (tile >> 2) * 8, tx0 = (tile & 3) * 8;
    int tid = threadIdx.x;

    for (int i = tid; i < 200; i += 256) {
        int ic = i / 100, r = (i / 10) % 10, c = i % 10;
        int gy = ty0 + r - 1, gx = tx0 + c - 1;
        float v = 0.f;
        if ((unsigned)gy < 32u && (unsigned)gx < 32u) {
            float d = data[(size_t)((((b*2 + ic)*32 + gy)*32 + gx)) * TWIN + t];
            v = (d > 1.0f) ? 1.0f : 0.0f;
        }
        xs[ic][r][c] = v;
    }
    for (int i = tid; i < 1152; i += 256) {
        int oc = i / 18, r = i % 18;
        ws[oc][r] = W0[i];
    }
    __syncthreads();

    int p  = tid & 63;
    int cg = tid >> 6;
    int py = p >> 3, px = p & 7;
    int oc0 = cg * 16;

    float acc[16];
#pragma unroll
    for (int o = 0; o < 16; o++) acc[o] = 0.f;

#pragma unroll
    for (int ic = 0; ic < 2; ic++) {
        float xr[9];
#pragma unroll
        for (int r = 0; r < 3; r++)
#pragma unroll
            for (int c = 0; c < 3; c++)
                xr[r*3 + c] = xs[ic][py + r][px + c];
#pragma unroll
        for (int k = 0; k < 9; k++) {
            float x = xr[k];
#pragma unroll
            for (int o = 0; o < 16; o++)
                acc[o] = fmaf(x, ws[oc0 + o][ic*9 + k], acc[o]);
        }
    }

    int gy = ty0 + py, gx = tx0 + px;
#pragma unroll
    for (int o = 0; o < 16; o++) {
        int oc = oc0 + o;
        int idx = ((b*64 + oc)*32 + gy)*32 + gx;
        g_act0[idx] = liaf_pre(acc[o] + b0[oc], &g_c0_pre[idx]);
    }
}

// ---------------- f32x2 conv (3x3) + LIAF + 2x2 pool + LIAF ----------------
// Tile 16 rows x 8 cols. Thread = 2x4 pixels x OCPT oc. 256 threads.
//   pos = tid & 15 : prow = pos>>1 (0..7), pcol = pos&1 (0..1)
//   g   = tid >> 4 : oc group, oc0 = g*OCPT (local)
// xs2: duplicated-x pairs, row stride 22 floats (8B-aligned 64-bit loads).
// ws:  [j(0..71)][OCTOT] oc-contiguous -> 64-bit loads give (w[oc],w[oc+1]).
template<int CIN, int HW, int OCTOT, int OCPT>
__device__ __forceinline__ void conv_pool_f2(
    const float* __restrict__ in, const float* __restrict__ Wt,
    const float* __restrict__ bias, float* __restrict__ conv_pre,
    float* __restrict__ pool_pre, float* __restrict__ pool_out,
    int ocbase, int t0r, int t0c)
{
    constexpr int NOG = OCPT / 2;
    __shared__ __align__(16) float xs2[8*18*22];
    __shared__ __align__(16) float ws[72*OCTOT];

    const int b   = blockIdx.y;
    const int tid = threadIdx.x;
    const int pos = tid & 15;
    const int g   = tid >> 4;
    const int prow = pos >> 1;
    const int pcol = pos & 1;
    const int oc0 = g * OCPT;

    ull acc[2][4][NOG];
#pragma unroll
    for (int py = 0; py < 2; py++)
#pragma unroll
        for (int px = 0; px < 4; px++)
#pragma unroll
            for (int og = 0; og < NOG; og++) acc[py][px][og] = 0ull;

    for (int ch = 0; ch < CIN/8; ch++) {
        __syncthreads();
        // stage input: 8 ch x 18 rows x 10 cols halo, duplicated pairs
        for (int i = tid; i < 1440; i += 256) {
            int icl = i / 180; int rem = i - icl*180;
            int r = rem / 10, c = rem - r*10;
            int gy = t0r + r - 1, gx = t0c + c - 1;
            float v = 0.f;
            if ((unsigned)gy < (unsigned)HW && (unsigned)gx < (unsigned)HW)
                v = in[((b*CIN + ch*8 + icl)*HW + gy)*HW + gx];
            float* p = &xs2[(icl*18 + r)*22 + c*2];
            p[0] = v; p[1] = v;
        }
        // stage weights: ws[j][0..OCTOT) = Wt[ch*72+j][ocbase..]; float4 both ways
        for (int i = tid; i < 72*(OCTOT/4); i += 256) {
            int j = i / (OCTOT/4), q = i - j*(OCTOT/4);
            *(float4*)&ws[j*OCTOT + q*4] =
                *(const float4*)&Wt[(ch*72 + j)*128 + ocbase + q*4];
        }
        __syncthreads();

#pragma unroll 1
        for (int icl = 0; icl < 8; icl++) {
            const float* xbase = &xs2[icl * (18*22)];
            const float* wbase = &ws[icl * (9*OCTOT) + oc0];
#pragma unroll
            for (int ky = 0; ky < 3; ky++) {
                ull xd[2][6];
#pragma unroll
                for (int r2 = 0; r2 < 2; r2++)
#pragma unroll
                    for (int c = 0; c < 6; c++)
                        xd[r2][c] = *(const ull*)
                            &xbase[(prow*2 + ky + r2)*22 + (pcol*4 + c)*2];
#pragma unroll
                for (int kx = 0; kx < 3; kx++) {
                    ull wp[NOG];
#pragma unroll
                    for (int og = 0; og < NOG; og++)
                        wp[og] = *(const ull*)&wbase[(ky*3 + kx)*OCTOT + og*2];
#pragma unroll
                    for (int py = 0; py < 2; py++)
#pragma unroll
                        for (int px = 0; px < 4; px++)
#pragma unroll
                            for (int og = 0; og < NOG; og++)
                                FMA2(acc[py][px][og], xd[py][px + kx], wp[og]);
                }
            }
        }
    }

    // epilogue: conv LIAF, then 2x2 pool + pool LIAF (order matches reference)
    const int pyo = (t0r >> 1) + prow;
#pragma unroll
    for (int og = 0; og < NOG; og++) {
#pragma unroll
        for (int half = 0; half < 2; half++) {
            int oc = ocbase + oc0 + og*2 + half;
            float bv = bias[oc];
            float a[2][4];
#pragma unroll
            for (int py = 0; py < 2; py++)
#pragma unroll
                for (int px = 0; px < 4; px++) {
                    F2 v; v.u = acc[py][px][og];
                    float u = (half ? v.f.y : v.f.x) + bv;
                    int gy = t0r + prow*2 + py, gx = t0c + pcol*4 + px;
                    int idx = ((b*128 + oc)*HW + gy)*HW + gx;
                    a[py][px] = liaf_pre(u, &conv_pre[idx]);
                }
#pragma unroll
            for (int w = 0; w < 2; w++) {
                float u = 0.25f * (((a[0][w*2] + a[0][w*2+1]) + a[1][w*2]) + a[1][w*2+1]);
                int pxo = (t0c >> 1) + pcol*2 + w;
                int pidx = ((b*128 + oc)*(HW/2) + pyo)*(HW/2) + pxo;
                pool_out[pidx] = liaf_pre(u, &pool_pre[pidx]);
            }
        }
    }
}

// conv1: 64->128, 32x32. grid (8, 36): tile = (bx>>2)*16 rows, (bx&3)*8 cols.
__global__ __launch_bounds__(256, 2) void conv1_kernel(const float* __restrict__ bias)
{
    int bx = blockIdx.x;
    conv_pool_f2<64, 32, 128, 8>(g_act0, g_Wt1, bias, g_c1_pre, g_p1_pre, g_actp1,
                                 0, (bx >> 2) * 16, (bx & 3) * 8);
}

// conv2: 128->128, 16x16. grid (4, 36): bx = tile*2 + ochalf.
__global__ __launch_bounds__(256, 2) void conv2_kernel(const float* __restrict__ bias)
{
    int bx = blockIdx.x;
    conv_pool_f2<128, 16, 64, 4>(g_actp1, g_Wt2, bias, g_c2_pre, g_p2_pre, g_actp2,
                                 (bx & 1) * 64, 0, (bx >> 1) * 8);
}

// ---------------- FC1: 8192 -> 256 + LIAF ----------------
// grid (64, 6), block 128: warp = one output o, loops 6 batches.
__global__ __launch_bounds__(128) void fc1_kernel(
    const float* __restrict__ Wf1, const float* __restrict__ bf1)
{
    int warp = threadIdx.x >> 5, lane = threadIdx.x & 31;
    int o = blockIdx.x * 4 + warp;
    const float4* wp = (const float4*)(Wf1 + (size_t)o * 8192);
    float bv = bf1[o];
    int b0 = blockIdx.y * 6;
    for (int b = b0; b < b0 + 6; b++) {
        const float4* xp = (const float4*)(g_actp2 + (size_t)b * 8192);
        float s = 0.f;
#pragma unroll 8
        for (int i = lane; i < 2048; i += 32) {
            float4 x = xp[i], w = wp[i];
            s += x.x*w.x; s += x.y*w.y; s += x.z*w.z; s += x.w*w.w;
        }
#pragma unroll
        for (int off = 16; off; off >>= 1) s += __shfl_down_sync(0xffffffffu, s, off);
        if (lane == 0) {
            int idx = b*256 + o;
            g_acth1[idx] = liaf_pre(s + bv, &g_h1_pre[idx]);
        }
    }
}

// ---------------- FC2: 256 -> 11 + LIAF + accumulate ----------------
__global__ void fc2_kernel(const float* __restrict__ Wf2, const float* __restrict__ bf2) {
    int b = blockIdx.x;
    int warp = threadIdx.x >> 5, lane = threadIdx.x & 31;
    if (warp >= 11) return;
    float s = 0.f;
#pragma unroll
    for (int k = lane; k < 256; k += 32)
        s += g_acth1[b*256 + k] * Wf2[warp*256 + k];
#pragma unroll
    for (int off = 16; off; off >>= 1) s += __shfl_down_sync(0xffffffffu, s, off);
    if (lane == 0) {
        int idx = b*11 + warp;
        float o = liaf_pre(s + bf2[warp], &g_h2_pre[idx]);
        g_acc[idx] += o;
    }
}

// ---------------- finalize ----------------
__global__ void finalize_kernel(float* __restrict__ out) {
    int i = threadIdx.x;
    if (i < BATCH*11) out[i] = g_acc[i] * (1.0f / (float)TWIN);
}

extern "C" void kernel_launch(void* const* d_in, const int* in_sizes, int n_in,
                              void* d_out, int out_size) {
    (void)in_sizes; (void)n_in; (void)out_size;
    const float* data = (const float*)d_in[0];
    const float* W0  = (const float*)d_in[2];
    const float* b0  = (const float*)d_in[3];
    const float* W1  = (const float*)d_in[4];
    const float* b1  = (const float*)d_in[5];
    const float* W2  = (const float*)d_in[6];
    const float* b2  = (const float*)d_in[7];
    const float* Wf1 = (const float*)d_in[8];
    const float* bf1 = (const float*)d_in[9];
    const float* Wf2 = (const float*)d_in[10];
    const float* bf2 = (const float*)d_in[11];

    zero_state_kernel<<<(BATCH*128*32*32 + 255)/256, 256>>>();
    prep_weights_kernel<<<(1152*128 + 255)/256, 256>>>(W1, W2);

    for (int t = 0; t < TWIN; t++) {
        conv0_kernel<<<dim3(16, BATCH), 256>>>(data, W0, b0, t);
        conv1_kernel<<<dim3(8, BATCH), 256>>>(b1);
        conv2_kernel<<<dim3(4, BATCH), 256>>>(b2);
        fc1_kernel<<<dim3(64, 6), 128>>>(Wf1, bf1);
        fc2_kernel<<<BATCH, 384>>>(Wf2, bf2);
    }

    finalize_kernel<<<1, 512>>>((float*)d_out);
}

// round 4
// speedup vs baseline: 2.6357x; 1.0884x over previous
#include <cuda_runtime.h>

typedef unsigned long long ull;

#define BATCH 36
#define TWIN 60
#define DECAY 0.3f
#define THRESH 0.5f

// packed f32x2 fma: d = a*b + d per 32-bit lane (bit-exact IEEE fma per lane)
#define FMA2(d, a, b) asm("fma.rn.f32x2 %0, %1, %2, %0;" : "+l"(d) : "l"(a), "l"(b))

union F2 { ull u; float2 f; };

__device__ __forceinline__ ull dup2(float v) {
    F2 d; d.f.x = v; d.f.y = v; return d.u;
}

// ---------------- persistent LIAF state: pre = (m>THRESH) ? 0 : m*DECAY ----------
// next membrane m' = pre + u  (bit-exact vs m*DECAY*(1-s)+u, s in {0,1})
__device__ __align__(16) float g_c0_pre[BATCH*64*32*32];
__device__ __align__(16) float g_c1_pre[BATCH*128*32*32];
__device__ __align__(16) float g_p1_pre[BATCH*128*16*16];
__device__ __align__(16) float g_c2_pre[BATCH*128*16*16];
__device__ __align__(16) float g_p2_pre[BATCH*128*8*8];
__device__ __align__(16) float g_h1_pre[BATCH*256];
__device__ __align__(16) float g_h2_pre[BATCH*11];
__device__ __align__(16) float g_acc[BATCH*11];

// ---------------- activations ----------------
__device__ __align__(16) float g_act0 [BATCH*64*32*32];
__device__ __align__(16) float g_actp1[BATCH*128*16*16];
__device__ __align__(16) float g_actp2[BATCH*128*8*8];
__device__ __align__(16) float g_acth1[BATCH*256];

// ---------------- transposed weights: Wt[c][oc], c = ic*9 + k ----------------
__device__ __align__(16) float g_Wt1[576*128];   // conv1: 64*9 x 128
__device__ __align__(16) float g_Wt2[1152*128];  // conv2: 128*9 x 128

__device__ __forceinline__ float liaf_pre(float u, float* prep) {
    float m = *prep + u;
    *prep = (m > THRESH) ? 0.0f : m * DECAY;
    return fmaxf(m, 0.0f);
}

// ---------------- zero state ----------------
__global__ void zero_state_kernel() {
    int i = blockIdx.x * blockDim.x + threadIdx.x;
    if (i < BATCH*64*32*32)  g_c0_pre[i] = 0.f;
    if (i < BATCH*128*32*32) g_c1_pre[i] = 0.f;
    if (i < BATCH*128*16*16) { g_p1_pre[i] = 0.f; g_c2_pre[i] = 0.f; }
    if (i < BATCH*128*8*8)   g_p2_pre[i] = 0.f;
    if (i < BATCH*256)       g_h1_pre[i] = 0.f;
    if (i < BATCH*11)        { g_h2_pre[i] = 0.f; g_acc[i] = 0.f; }
}

// ---------------- weight transpose (once per launch) ----------------
__global__ void prep_weights_kernel(const float* __restrict__ W1,
                                    const float* __restrict__ W2) {
    int i = blockIdx.x * blockDim.x + threadIdx.x;
    if (i < 576*128)  g_Wt1[i] = W1[(i & 127)*576  + (i >> 7)];
    if (i < 1152*128) g_Wt2[i] = W2[(i & 127)*1152 + (i >> 7)];
}

// ---------------- conv0: binarize + 2->64 conv + LIAF ----------------
__global__ __launch_bounds__(256) void conv0_kernel(
    const float* __restrict__ data, const float* __restrict__ W0,
    const float* __restrict__ b0, int t)
{
    __shared__ float xs[2][10][12];
    __shared__ float ws[64][19];
    int tile = blockIdx.x, b = blockIdx.y;
    int ty0 = (tile >> 2) * 8, tx0 = (tile & 3) * 8;
    int tid = threadIdx.x;

    for (int i = tid; i < 200; i += 256) {
        int ic = i / 100, r = (i / 10) % 10, c = i % 10;
        int gy = ty0 + r - 1, gx = tx0 + c - 1;
        float v = 0.f;
        if ((unsigned)gy < 32u && (unsigned)gx < 32u) {
            float d = data[(size_t)((((b*2 + ic)*32 + gy)*32 + gx)) * TWIN + t];
            v = (d > 1.0f) ? 1.0f : 0.0f;
        }
        xs[ic][r][c] = v;
    }
    for (int i = tid; i < 1152; i += 256) {
        int oc = i / 18, r = i % 18;
        ws[oc][r] = W0[i];
    }
    __syncthreads();

    int p  = tid & 63;
    int cg = tid >> 6;
    int py = p >> 3, px = p & 7;
    int oc0 = cg * 16;

    float acc[16];
#pragma unroll
    for (int o = 0; o < 16; o++) acc[o] = 0.f;

#pragma unroll
    for (int ic = 0; ic < 2; ic++) {
        float xr[9];
#pragma unroll
        for (int r = 0; r < 3; r++)
#pragma unroll
            for (int c = 0; c < 3; c++)
                xr[r*3 + c] = xs[ic][py + r][px + c];
#pragma unroll
        for (int k = 0; k < 9; k++) {
            float x = xr[k];
#pragma unroll
            for (int o = 0; o < 16; o++)
                acc[o] = fmaf(x, ws[oc0 + o][ic*9 + k], acc[o]);
        }
    }

    int gy = ty0 + py, gx = tx0 + px;
#pragma unroll
    for (int o = 0; o < 16; o++) {
        int oc = oc0 + o;
        int idx = ((b*64 + oc)*32 + gy)*32 + gx;
        g_act0[idx] = liaf_pre(acc[o] + b0[oc], &g_c0_pre[idx]);
    }
}

// ---------------- f32x2 conv (3x3) + LIAF + 2x2 pool + LIAF, v2 ----------------
// Block 256. Tile TILE_R x 8. Thread = 2 x PXC pixels x 4 oc (oc packed in pairs).
//   pos = tid & 15 -> (prow, pcol); g = tid >> 4 -> oc group (4 oc each, 64 total)
// xs: scalar (no dup), row stride 13 (bank-skewed); x pairs (x,x) built in regs.
// ws: [j 0..71][64 oc] oc-contiguous; 64-bit broadcast loads give (w[oc],w[oc+1]).
template<int HW, int TILE_R, int PXC, int CIN>
__device__ __forceinline__ void conv_pool_v2(
    const float* __restrict__ in, const float* __restrict__ Wt,
    const float* __restrict__ bias, float* __restrict__ conv_pre,
    float* __restrict__ pool_pre, float* __restrict__ pool_out,
    int ocbase, int t0r, int t0c)
{
    constexpr int XROWS = TILE_R + 2;
    constexpr int XSTR  = 13;
    constexpr int PCOLS = 8 / PXC;
    __shared__ __align__(16) float xs[8 * XROWS * XSTR];
    __shared__ __align__(16) float ws[72 * 64];

    const int b    = blockIdx.y;
    const int tid  = threadIdx.x;
    const int pos  = tid & 15;
    const int g    = tid >> 4;
    const int prow = pos / PCOLS;
    const int pcol = pos % PCOLS;
    const int qy   = prow * 2;
    const int qx   = pcol * PXC;

    ull acc[2][PXC][2];
#pragma unroll
    for (int py = 0; py < 2; py++)
#pragma unroll
        for (int px = 0; px < PXC; px++) {
            acc[py][px][0] = 0ull; acc[py][px][1] = 0ull;
        }

    for (int ch = 0; ch < CIN/8; ch++) {
        __syncthreads();
        // stage x: 8 ch x XROWS x 10 cols (halo, zero-pad), scalar
        for (int i = tid; i < 8 * XROWS * 10; i += 256) {
            int icl = i / (XROWS * 10);
            int rem = i - icl * (XROWS * 10);
            int r = rem / 10, c = rem - r * 10;
            int gy = t0r + r - 1, gx = t0c + c - 1;
            float v = 0.f;
            if ((unsigned)gy < (unsigned)HW && (unsigned)gx < (unsigned)HW)
                v = in[((b*CIN + ch*8 + icl)*HW + gy)*HW + gx];
            xs[(icl * XROWS + r) * XSTR + c] = v;
        }
        // stage w: 72 rows x 64 oc, float4 both sides
        for (int i = tid; i < 72 * 16; i += 256) {
            int j = i >> 4, q = i & 15;
            *(float4*)&ws[j*64 + q*4] =
                *(const float4*)&Wt[(ch*72 + j)*128 + ocbase + q*4];
        }
        __syncthreads();

#pragma unroll 1
        for (int icl = 0; icl < 8; icl++) {
            const float* xb = &xs[icl * (XROWS * XSTR)];
            const float* wb = &ws[icl * (9*64) + g*4];
#pragma unroll
            for (int ky = 0; ky < 3; ky++) {
                ull xd[2][PXC + 2];
#pragma unroll
                for (int r2 = 0; r2 < 2; r2++)
#pragma unroll
                    for (int c = 0; c < PXC + 2; c++)
                        xd[r2][c] = dup2(xb[(qy + ky + r2) * XSTR + qx + c]);
#pragma unroll
                for (int kx = 0; kx < 3; kx++) {
                    ull w0 = *(const ull*)&wb[(ky*3 + kx)*64];
                    ull w1 = *(const ull*)&wb[(ky*3 + kx)*64 + 2];
#pragma unroll
                    for (int py = 0; py < 2; py++)
#pragma unroll
                        for (int px = 0; px < PXC; px++) {
                            FMA2(acc[py][px][0], xd[py][px + kx], w0);
                            FMA2(acc[py][px][1], xd[py][px + kx], w1);
                        }
                }
            }
        }
    }

    // epilogue: conv LIAF, then 2x2 pool + pool LIAF (reference order)
    const int gy0 = t0r + qy, gx0 = t0c + qx;
#pragma unroll
    for (int og = 0; og < 2; og++) {
#pragma unroll
        for (int half = 0; half < 2; half++) {
            int oc = ocbase + g*4 + og*2 + half;
            float bv = bias[oc];
            float a[2][PXC];
#pragma unroll
            for (int py = 0; py < 2; py++)
#pragma unroll
                for (int px = 0; px < PXC; px++) {
                    F2 v; v.u = acc[py][px][og];
                    float u = (half ? v.f.y : v.f.x) + bv;
                    int idx = ((b*128 + oc)*HW + gy0 + py)*HW + gx0 + px;
                    a[py][px] = liaf_pre(u, &conv_pre[idx]);
                }
#pragma unroll
            for (int w = 0; w < PXC/2; w++) {
                float u = 0.25f * (((a[0][w*2] + a[0][w*2+1]) + a[1][w*2]) + a[1][w*2+1]);
                int pidx = ((b*128 + oc)*(HW/2) + (gy0 >> 1))*(HW/2) + (gx0 >> 1) + w;
                pool_out[pidx] = liaf_pre(u, &pool_pre[pidx]);
            }
        }
    }
}

// conv1: 64->128, 32x32, tile 16x8, grid (16, 36): bx = ((tr*4)+tc)*2 + half
__global__ __launch_bounds__(256, 3) void conv1_kernel(const float* __restrict__ bias)
{
    int bx = blockIdx.x;
    int half = bx & 1, tc = (bx >> 1) & 3, tr = bx >> 3;
    conv_pool_v2<32, 16, 4, 64>(g_act0, g_Wt1, bias, g_c1_pre, g_p1_pre, g_actp1,
                                half * 64, tr * 16, tc * 8);
}

// conv2: 128->128, 16x16, tile 8x8, grid (8, 36): bx = ((tr*2)+tc)*2 + half
__global__ __launch_bounds__(256, 4) void conv2_kernel(const float* __restrict__ bias)
{
    int bx = blockIdx.x;
    int half = bx & 1, tc = (bx >> 1) & 1, tr = bx >> 2;
    conv_pool_v2<16, 8, 2, 128>(g_actp1, g_Wt2, bias, g_c2_pre, g_p2_pre, g_actp2,
                                half * 64, tr * 8, tc * 8);
}

// ---------------- FC1: 8192 -> 256 + LIAF ----------------
// grid (64, 6), block 128: warp = one output o, loops 6 batches.
__global__ __launch_bounds__(128) void fc1_kernel(
    const float* __restrict__ Wf1, const float* __restrict__ bf1)
{
    int warp = threadIdx.x >> 5, lane = threadIdx.x & 31;
    int o = blockIdx.x * 4 + warp;
    const float4* wp = (const float4*)(Wf1 + (size_t)o * 8192);
    float bv = bf1[o];
    int b0 = blockIdx.y * 6;
    for (int b = b0; b < b0 + 6; b++) {
        const float4* xp = (const float4*)(g_actp2 + (size_t)b * 8192);
        float s = 0.f;
#pragma unroll 8
        for (int i = lane; i < 2048; i += 32) {
            float4 x = xp[i], w = wp[i];
            s += x.x*w.x; s += x.y*w.y; s += x.z*w.z; s += x.w*w.w;
        }
#pragma unroll
        for (int off = 16; off; off >>= 1) s += __shfl_down_sync(0xffffffffu, s, off);
        if (lane == 0) {
            int idx = b*256 + o;
            g_acth1[idx] = liaf_pre(s + bv, &g_h1_pre[idx]);
        }
    }
}

// ---------------- FC2: 256 -> 11 + LIAF + accumulate ----------------
__global__ void fc2_kernel(const float* __restrict__ Wf2, const float* __restrict__ bf2) {
    int b = blockIdx.x;
    int warp = threadIdx.x >> 5, lane = threadIdx.x & 31;
    if (warp >= 11) return;
    float s = 0.f;
#pragma unroll
    for (int k = lane; k < 256; k += 32)
        s += g_acth1[b*256 + k] * Wf2[warp*256 + k];
#pragma unroll
    for (int off = 16; off; off >>= 1) s += __shfl_down_sync(0xffffffffu, s, off);
    if (lane == 0) {
        int idx = b*11 + warp;
        float o = liaf_pre(s + bf2[warp], &g_h2_pre[idx]);
        g_acc[idx] += o;
    }
}

// ---------------- finalize ----------------
__global__ void finalize_kernel(float* __restrict__ out) {
    int i = threadIdx.x;
    if (i < BATCH*11) out[i] = g_acc[i] * (1.0f / (float)TWIN);
}

extern "C" void kernel_launch(void* const* d_in, const int* in_sizes, int n_in,
                              void* d_out, int out_size) {
    (void)in_sizes; (void)n_in; (void)out_size;
    const float* data = (const float*)d_in[0];
    const float* W0  = (const float*)d_in[2];
    const float* b0  = (const float*)d_in[3];
    const float* W1  = (const float*)d_in[4];
    const float* b1  = (const float*)d_in[5];
    const float* W2  = (const float*)d_in[6];
    const float* b2  = (const float*)d_in[7];
    const float* Wf1 = (const float*)d_in[8];
    const float* bf1 = (const float*)d_in[9];
    const float* Wf2 = (const float*)d_in[10];
    const float* bf2 = (const float*)d_in[11];

    zero_state_kernel<<<(BATCH*128*32*32 + 255)/256, 256>>>();
    prep_weights_kernel<<<(1152*128 + 255)/256, 256>>>(W1, W2);

    for (int t = 0; t < TWIN; t++) {
        conv0_kernel<<<dim3(16, BATCH), 256>>>(data, W0, b0, t);
        conv1_kernel<<<dim3(16, BATCH), 256>>>(b1);
        conv2_kernel<<<dim3(8, BATCH), 256>>>(b2);
        fc1_kernel<<<dim3(64, 6), 128>>>(Wf1, bf1);
        fc2_kernel<<<BATCH, 384>>>(Wf2, bf2);
    }

    finalize_kernel<<<1, 512>>>((float*)d_out);
}